// round 8
// baseline (speedup 1.0000x reference)
#include <cuda_runtime.h>
#include <cuda_bf16.h>
#include <cstdint>

// Problem constants
#define BATCH 16
#define TT    8192
#define HH    256
#define HQ    64
#define KSLOT 128
#define TILE  32                        // tokens per tile
#define NT32  (BATCH * (TT / TILE))     // 4096 tiles
#define NB1   (TT / 16)                 // 512 fine blocks (16 tokens)
#define NSB   (TT / 256)                // 32 superblocks
#define SROWA 260                       // fp32 words per smem row (pad 4)
#define XT_WORDS (TILE * SROWA)         // 8320
#define SDROW 68                        // partial-grid row stride (words)

// Scratch
__device__ float d_e [BATCH * TT];
__device__ float d_S [BATCH * NB1 * HH];
__device__ float d_E [BATCH * NB1];
__device__ float d_S2[BATCH * NSB * HH];
__device__ float d_E2[BATCH * NSB];

__device__ __forceinline__ float tf32r(float x) {
    float r; asm("cvt.rna.tf32.f32 %0, %1;" : "=f"(r) : "f"(x)); return r;
}
__device__ __forceinline__ float tanha(float x) {
    float r; asm("tanh.approx.f32 %0, %1;" : "=f"(r) : "f"(x)); return r;
}
__device__ __forceinline__ void cpa16(uint32_t dst, const float* src) {
    asm volatile("cp.async.cg.shared.global [%0], [%1], 16;" :: "r"(dst), "l"(src));
}

// smem: sX[2][32][SROWA] | sD[4][32][SDROW] | sE[32] | sB1[64] | sW2[64]
#define SMEM_A_WORDS (2 * XT_WORDS + 4 * 32 * SDROW + 32 + 64 + 64)
#define SMEM_A_BYTES (SMEM_A_WORDS * 4)

__global__ void __launch_bounds__(256, 2) pass_a_kernel(
    const float* __restrict__ x,
    const float* __restrict__ W1,
    const float* __restrict__ b1,
    const float* __restrict__ W2,
    const float* __restrict__ b2)
{
    extern __shared__ float sm[];
    float* sXbuf[2] = { sm, sm + XT_WORDS };
    float* sD  = sm + 2 * XT_WORDS;          // [4][32][SDROW]
    float* sE  = sD + 4 * 32 * SDROW;        // [32]
    float* sB1 = sE + 32;
    float* sW2 = sB1 + 64;

    const int tid  = threadIdx.x;
    const int warp = tid >> 5;           // 0..7
    const int lane = tid & 31;
    const int g    = lane >> 2;          // 0..7
    const int q    = lane & 3;           // 0..3
    const int kq   = warp & 3;           // K quarter: k in [kq*64, kq*64+64)
    const int nh   = warp >> 2;          // n half: cols [nh*32, nh*32+32)

    uint32_t smem_u32;
    { uint64_t t64; asm("cvta.to.shared.u64 %0, %1;" : "=l"(t64) : "l"(sm));
      smem_u32 = (uint32_t)t64; }

    // epilogue constants to smem
    if (tid < 64) { sB1[tid] = b1[tid]; sW2[tid] = W2[tid]; }

    // --- W1 register-resident B fragments: warp covers 64 k x 32 n ---
    uint32_t Breg[8][4][2];
    #pragma unroll
    for (int kt = 0; kt < 8; kt++)
        #pragma unroll
        for (int nt = 0; nt < 4; nt++) {
            const int n = nh * 32 + nt * 8 + g;
            const int k = kq * 64 + kt * 8 + q;
            Breg[kt][nt][0] = __float_as_uint(tf32r(W1[(k)     * HQ + n]));
            Breg[kt][nt][1] = __float_as_uint(tf32r(W1[(k + 4) * HQ + n]));
        }

    // epilogue role: thread owns (token, 8-col group)
    const int etok = (warp << 2) | (lane >> 3);   // 0..31
    const int ecg  = lane & 7;                    // 0..7
    const int ec0  = ecg * 8;
    const float bb2 = b2[0];

    int tile = blockIdx.x;
    {   // prefetch first tile into buf 0 (256 thr x 8 chunks of 16B)
        const float* src = x + (size_t)tile * (TILE * HH);
        #pragma unroll
        for (int i = 0; i < 8; i++) {
            const int off = i * 1024 + tid * 4;
            const int r = off >> 8, c = off & 255;
            cpa16(smem_u32 + (uint32_t)(r * SROWA + c) * 4, src + off);
        }
        asm volatile("cp.async.commit_group;");
    }

    int buf = 0;
    for (; tile < NT32; tile += gridDim.x, buf ^= 1) {
        float* sX  = sXbuf[buf];
        const int next = tile + gridDim.x;

        __syncthreads();   // prev tile fully consumed (other buf, sD, sE free)

        if (next < NT32) {
            const float* src = x + (size_t)next * (TILE * HH);
            const uint32_t base = smem_u32 + (uint32_t)((buf ^ 1) * XT_WORDS) * 4;
            #pragma unroll
            for (int i = 0; i < 8; i++) {
                const int off = i * 1024 + tid * 4;
                const int r = off >> 8, c = off & 255;
                cpa16(base + (uint32_t)(r * SROWA + c) * 4, src + off);
            }
            asm volatile("cp.async.commit_group;");
            asm volatile("cp.async.wait_group 1;");
        } else {
            asm volatile("cp.async.wait_group 0;");
        }
        __syncthreads();   // current buffer visible

        // --- MMA: warp computes 32 tokens x 32 n-cols over its K quarter ---
        float acc[2][4][4];
        #pragma unroll
        for (int m = 0; m < 2; m++)
            #pragma unroll
            for (int nt = 0; nt < 4; nt++)
                #pragma unroll
                for (int i = 0; i < 4; i++) acc[m][nt][i] = 0.f;

        #pragma unroll
        for (int kt = 0; kt < 8; kt++) {
            const int kb = kq * 64 + kt * 8 + q;
            #pragma unroll
            for (int m = 0; m < 2; m++) {
                const int rl = m * 16 + g;
                uint32_t a0 = __float_as_uint(sX[(rl)     * SROWA + kb]);
                uint32_t a1 = __float_as_uint(sX[(rl + 8) * SROWA + kb]);
                uint32_t a2 = __float_as_uint(sX[(rl)     * SROWA + kb + 4]);
                uint32_t a3 = __float_as_uint(sX[(rl + 8) * SROWA + kb + 4]);
                #pragma unroll
                for (int nt = 0; nt < 4; nt++) {
                    asm volatile(
                        "mma.sync.aligned.m16n8k8.row.col.f32.tf32.tf32.f32 "
                        "{%0,%1,%2,%3},{%4,%5,%6,%7},{%8,%9},{%0,%1,%2,%3};"
                        : "+f"(acc[m][nt][0]), "+f"(acc[m][nt][1]),
                          "+f"(acc[m][nt][2]), "+f"(acc[m][nt][3])
                        : "r"(a0), "r"(a1), "r"(a2), "r"(a3),
                          "r"(Breg[kt][nt][0]), "r"(Breg[kt][nt][1]));
                }
            }
        }

        // --- symmetric partial store: all warps -> sD[kq][tok][col] ---
        #pragma unroll
        for (int m = 0; m < 2; m++)
            #pragma unroll
            for (int nt = 0; nt < 4; nt++) {
                const int c = nh * 32 + nt * 8 + 2 * q;
                float* p0 = &sD[(kq * 32 + m * 16 + g)     * SDROW + c];
                float* p1 = &sD[(kq * 32 + m * 16 + g + 8) * SDROW + c];
                *(float2*)p0 = make_float2(acc[m][nt][0], acc[m][nt][1]);
                *(float2*)p1 = make_float2(acc[m][nt][2], acc[m][nt][3]);
            }
        __syncthreads();

        const int b     = tile >> 8;         // batch (TT/TILE = 256)
        const int blk32 = tile & 255;

        // --- balanced epilogue: 256 threads, each (token, 8 cols) ---
        {
            float4 a0 = make_float4(0.f, 0.f, 0.f, 0.f);
            float4 a1 = make_float4(0.f, 0.f, 0.f, 0.f);
            #pragma unroll
            for (int kk = 0; kk < 4; kk++) {
                const float4* p = (const float4*)&sD[(kk * 32 + etok) * SDROW + ec0];
                float4 u = p[0], v = p[1];
                a0.x += u.x; a0.y += u.y; a0.z += u.z; a0.w += u.w;
                a1.x += v.x; a1.y += v.y; a1.z += v.z; a1.w += v.w;
            }
            const float4 bA = *(const float4*)&sB1[ec0];
            const float4 bB = *(const float4*)&sB1[ec0 + 4];
            const float4 wA = *(const float4*)&sW2[ec0];
            const float4 wB = *(const float4*)&sW2[ec0 + 4];
            float s = tanha(a0.x + bA.x) * wA.x + tanha(a0.y + bA.y) * wA.y
                    + tanha(a0.z + bA.z) * wA.z + tanha(a0.w + bA.w) * wA.w
                    + tanha(a1.x + bB.x) * wB.x + tanha(a1.y + bB.y) * wB.y
                    + tanha(a1.z + bB.z) * wB.z + tanha(a1.w + bB.w) * wB.w;
            s += __shfl_xor_sync(0xffffffffu, s, 1);
            s += __shfl_xor_sync(0xffffffffu, s, 2);
            s += __shfl_xor_sync(0xffffffffu, s, 4);
            if (ecg == 0) {
                const float e = __expf(s + bb2);
                sE[etok] = e;
                d_e[b * TT + blk32 * TILE + etok] = e;
            }
        }
        __syncthreads();

        // --- two 16-token block partial sums, all 256 threads ---
        #pragma unroll
        for (int j = 0; j < 2; j++) {
            float a = 0.f, den = 0.f;
            #pragma unroll
            for (int t = j * 16; t < j * 16 + 16; t++) {
                const float e = sE[t];
                a   += e * sX[t * SROWA + tid];
                den += e;
            }
            const int bi = b * NB1 + blk32 * 2 + j;
            d_S[(size_t)bi * HH + tid] = a;
            if (tid == 0) d_E[bi] = den;
        }
    }
}

// Aggregate 16 fine blocks -> 1 superblock
__global__ void __launch_bounds__(256) pass_ab_kernel()
{
    const int sb  = blockIdx.x & (NSB - 1);
    const int b   = blockIdx.x >> 5;
    const int tid = threadIdx.x;

    const float* Sb = d_S + ((size_t)(b * NB1 + sb * 16)) * HH + tid;
    float s0 = 0.f, s1 = 0.f, s2 = 0.f, s3 = 0.f;
    #pragma unroll
    for (int i = 0; i < 16; i += 4) {
        s0 += Sb[(size_t)(i + 0) * HH];
        s1 += Sb[(size_t)(i + 1) * HH];
        s2 += Sb[(size_t)(i + 2) * HH];
        s3 += Sb[(size_t)(i + 3) * HH];
    }
    d_S2[(size_t)(b * NSB + sb) * HH + tid] = (s0 + s1) + (s2 + s3);
    if (tid == 0) {
        float e = 0.f;
        #pragma unroll
        for (int i = 0; i < 16; i++) e += d_E[b * NB1 + sb * 16 + i];
        d_E2[b * NSB + sb] = e;
    }
}

__global__ void __launch_bounds__(256) pass_b_kernel(
    const float* __restrict__ x,
    const int*   __restrict__ boundaries,
    const int*   __restrict__ slot_mask,
    float*       __restrict__ out)
{
    const int k   = blockIdx.x;
    const int b   = blockIdx.y;
    const int tid = threadIdx.x;     // h index

    const int sidx  = b * KSLOT + k;
    const int start = boundaries[sidx * 2];
    const int end   = boundaries[sidx * 2 + 1];
    const int mask  = slot_mask[sidx];

    float* o = out + (size_t)sidx * HH;
    if (mask <= 0 || start >= end) { o[tid] = 0.f; return; }

    const float* xb  = x    + (size_t)b * TT * HH;
    const float* eb  = d_e  + b * TT;
    const float* Sb1 = d_S  + (size_t)b * NB1 * HH;
    const float* Eb1 = d_E  + b * NB1;
    const float* Sb2 = d_S2 + (size_t)b * NSB * HH;
    const float* Eb2 = d_E2 + b * NSB;

    float acc = 0.f, den = 0.f;

    auto tokens = [&](int t0, int t1) {
        float ea = 0.f, ec = 0.f, da = 0.f, dc = 0.f;
        int t = t0;
        for (; t + 2 <= t1; t += 2) {
            const float e0 = eb[t], e1 = eb[t + 1];
            ea += e0 * xb[(size_t)(t)     * HH + tid]; da += e0;
            ec += e1 * xb[(size_t)(t + 1) * HH + tid]; dc += e1;
        }
        if (t < t1) { const float e = eb[t]; ea += e * xb[(size_t)t * HH + tid]; da += e; }
        acc += ea + ec; den += da + dc;
    };
    auto blocks = [&](int i0, int i1) {
        float a0 = 0.f, a1 = 0.f, d0 = 0.f, d1 = 0.f;
        int i = i0;
        for (; i + 2 <= i1; i += 2) {
            a0 += Sb1[(size_t)(i)     * HH + tid]; d0 += Eb1[i];
            a1 += Sb1[(size_t)(i + 1) * HH + tid]; d1 += Eb1[i + 1];
        }
        if (i < i1) { a0 += Sb1[(size_t)i * HH + tid]; d0 += Eb1[i]; }
        acc += a0 + a1; den += d0 + d1;
    };

    const int fb = (start + 15) >> 4;
    const int lb = end >> 4;

    if (fb >= lb) {
        tokens(start, end);
    } else {
        tokens(start, fb * 16);
        tokens(lb * 16, end);

        const int fs = (fb + 15) >> 4;
        const int ls = lb >> 4;
        if (fs >= ls) {
            blocks(fb, lb);
        } else {
            blocks(fb, fs * 16);
            blocks(ls * 16, lb);
            float a0 = 0.f, a1 = 0.f, a2 = 0.f, a3 = 0.f;
            float d0 = 0.f, d1 = 0.f, d2 = 0.f, d3 = 0.f;
            int i = fs;
            for (; i + 4 <= ls; i += 4) {
                a0 += Sb2[(size_t)(i + 0) * HH + tid]; d0 += Eb2[i + 0];
                a1 += Sb2[(size_t)(i + 1) * HH + tid]; d1 += Eb2[i + 1];
                a2 += Sb2[(size_t)(i + 2) * HH + tid]; d2 += Eb2[i + 2];
                a3 += Sb2[(size_t)(i + 3) * HH + tid]; d3 += Eb2[i + 3];
            }
            for (; i < ls; i++) { a0 += Sb2[(size_t)i * HH + tid]; d0 += Eb2[i]; }
            acc += (a0 + a1) + (a2 + a3);
            den += (d0 + d1) + (d2 + d3);
        }
    }

    o[tid] = acc / den;   // den > 0: end > start and all e_t > 0
}

extern "C" void kernel_launch(void* const* d_in, const int* in_sizes, int n_in,
                              void* d_out, int out_size)
{
    const float* x          = (const float*)d_in[0];
    const int*   boundaries = (const int*)d_in[1];
    const int*   slot_mask  = (const int*)d_in[2];
    const float* W1         = (const float*)d_in[3];
    const float* b1         = (const float*)d_in[4];
    const float* W2         = (const float*)d_in[5];
    const float* b2         = (const float*)d_in[6];
    float* out = (float*)d_out;

    cudaFuncSetAttribute(pass_a_kernel,
                         cudaFuncAttributeMaxDynamicSharedMemorySize,
                         SMEM_A_BYTES);

    pass_a_kernel<<<296, 256, SMEM_A_BYTES>>>(x, W1, b1, W2, b2);
    pass_ab_kernel<<<BATCH * NSB, 256>>>();
    pass_b_kernel<<<dim3(KSLOT, BATCH), 256>>>(x, boundaries, slot_mask, out);
}

// round 9
// speedup vs baseline: 1.0226x; 1.0226x over previous
#include <cuda_runtime.h>
#include <cuda_bf16.h>
#include <cstdint>

// Problem constants
#define BATCH 16
#define TT    8192
#define HH    256
#define HQ    64
#define KSLOT 128
#define TILE  32                        // tokens per tile
#define NT32  (BATCH * (TT / TILE))     // 4096 tiles
#define NB1   (TT / 16)                 // 512 fine blocks (16 tokens)
#define NSB   (TT / 256)                // 32 superblocks
#define SROWA 260                       // fp32 words per smem row (pad 4)
#define XT_WORDS (TILE * SROWA)         // 8320
#define EXR   36                        // exchange slot stride (words)

// Scratch
__device__ float d_e [BATCH * TT];
__device__ float d_S [BATCH * NB1 * HH];
__device__ float d_E [BATCH * NB1];
__device__ float d_S2[BATCH * NSB * HH];
__device__ float d_E2[BATCH * NSB];

__device__ __forceinline__ float tf32r(float x) {
    float r; asm("cvt.rna.tf32.f32 %0, %1;" : "=f"(r) : "f"(x)); return r;
}
__device__ __forceinline__ float tanha(float x) {
    float r; asm("tanh.approx.f32 %0, %1;" : "=f"(r) : "f"(x)); return r;
}
__device__ __forceinline__ void cpa16(uint32_t dst, const float* src) {
    asm volatile("cp.async.cg.shared.global [%0], [%1], 16;" :: "r"(dst), "l"(src));
}
#define MMA_TF32(acc, a0, a1, a2, a3, b0, b1) \
    asm volatile( \
        "mma.sync.aligned.m16n8k8.row.col.f32.tf32.tf32.f32 " \
        "{%0,%1,%2,%3},{%4,%5,%6,%7},{%8,%9},{%0,%1,%2,%3};" \
        : "+f"((acc)[0]), "+f"((acc)[1]), "+f"((acc)[2]), "+f"((acc)[3]) \
        : "r"(a0), "r"(a1), "r"(a2), "r"(a3), "r"(b0), "r"(b1))

// smem: sX[2][32][SROWA] | sEx[6*32*EXR] | sE[32] | sP[32*2] | sB1[64] | sW2[64]
#define SMEM_A_WORDS (2 * XT_WORDS + 6 * 32 * EXR + 32 + 64 + 64 + 64)
#define SMEM_A_BYTES (SMEM_A_WORDS * 4)

__global__ void __launch_bounds__(256, 2) pass_a_kernel(
    const float* __restrict__ x,
    const float* __restrict__ W1,
    const float* __restrict__ b1,
    const float* __restrict__ W2,
    const float* __restrict__ b2)
{
    extern __shared__ float sm[];
    float* sXbuf[2] = { sm, sm + XT_WORDS };
    float* sEx = sm + 2 * XT_WORDS;
    float* sE  = sEx + 6 * 32 * EXR;
    float* sP  = sE + 32;
    float* sB1 = sP + 64;
    float* sW2 = sB1 + 64;

    const int tid  = threadIdx.x;
    const int warp = tid >> 5;           // 0..7
    const int lane = tid & 31;
    const int g    = lane >> 2;          // 0..7
    const int q    = lane & 3;           // 0..3
    const int kq   = warp >> 1;          // K quarter (epilogue warps 0,1 -> SMSP 0,1)
    const int nh   = warp & 1;           // n half: cols [nh*32, nh*32+32)

    uint32_t smem_u32;
    { uint64_t t64; asm("cvta.to.shared.u64 %0, %1;" : "=l"(t64) : "l"(sm));
      smem_u32 = (uint32_t)t64; }

    // epilogue constants to smem
    if (tid < 64) { sB1[tid] = b1[tid]; sW2[tid] = W2[tid]; }

    // --- W1 register-resident B fragments: warp covers 64 k x 32 n ---
    uint32_t Breg[8][4][2];
    #pragma unroll
    for (int kt = 0; kt < 8; kt++)
        #pragma unroll
        for (int nt = 0; nt < 4; nt++) {
            const int n = nh * 32 + nt * 8 + g;
            const int k = kq * 64 + kt * 8 + q;
            Breg[kt][nt][0] = __float_as_uint(tf32r(W1[(k)     * HQ + n]));
            Breg[kt][nt][1] = __float_as_uint(tf32r(W1[(k + 4) * HQ + n]));
        }
    const float bb2 = b2[0];

    int tile = blockIdx.x;
    {   // prefetch first tile into buf 0 (256 thr x 8 chunks of 16B)
        const float* src = x + (size_t)tile * (TILE * HH);
        #pragma unroll
        for (int i = 0; i < 8; i++) {
            const int off = i * 1024 + tid * 4;
            const int r = off >> 8, c = off & 255;
            cpa16(smem_u32 + (uint32_t)(r * SROWA + c) * 4, src + off);
        }
        asm volatile("cp.async.commit_group;");
    }

    int buf = 0;
    for (; tile < NT32; tile += gridDim.x, buf ^= 1) {
        float* sX  = sXbuf[buf];
        const int next = tile + gridDim.x;

        __syncthreads();   // prev tile fully consumed

        if (next < NT32) {
            const float* src = x + (size_t)next * (TILE * HH);
            const uint32_t base = smem_u32 + (uint32_t)((buf ^ 1) * XT_WORDS) * 4;
            #pragma unroll
            for (int i = 0; i < 8; i++) {
                const int off = i * 1024 + tid * 4;
                const int r = off >> 8, c = off & 255;
                cpa16(base + (uint32_t)(r * SROWA + c) * 4, src + off);
            }
            asm volatile("cp.async.commit_group;");
            asm volatile("cp.async.wait_group 1;");
        } else {
            asm volatile("cp.async.wait_group 0;");
        }
        __syncthreads();   // current buffer visible

        // --- MMA: warp computes 32 tokens x 32 n-cols over its K quarter ---
        float acc[2][4][4];
        #pragma unroll
        for (int m = 0; m < 2; m++)
            #pragma unroll
            for (int nt = 0; nt < 4; nt++)
                #pragma unroll
                for (int i = 0; i < 4; i++) acc[m][nt][i] = 0.f;

        #pragma unroll
        for (int kt = 0; kt < 8; kt++) {
            const int kb = kq * 64 + kt * 8 + q;
            #pragma unroll
            for (int m = 0; m < 2; m++) {
                const int rl = m * 16 + g;
                uint32_t a0 = __float_as_uint(sX[(rl)     * SROWA + kb]);
                uint32_t a1 = __float_as_uint(sX[(rl + 8) * SROWA + kb]);
                uint32_t a2 = __float_as_uint(sX[(rl)     * SROWA + kb + 4]);
                uint32_t a3 = __float_as_uint(sX[(rl + 8) * SROWA + kb + 4]);
                #pragma unroll
                for (int nt = 0; nt < 4; nt++)
                    MMA_TF32(acc[m][nt], a0, a1, a2, a3,
                             Breg[kt][nt][0], Breg[kt][nt][1]);
            }
        }

        // --- K-quarter exchange: kq=1..3 ship partials to kq=0 warps ---
        if (kq > 0) {
            float* slot = sEx + ((nh * 3 + (kq - 1)) * 32 + lane) * EXR;
            #pragma unroll
            for (int m = 0; m < 2; m++)
                #pragma unroll
                for (int nt = 0; nt < 4; nt++)
                    *(float4*)(slot + (m * 4 + nt) * 4) =
                        make_float4(acc[m][nt][0], acc[m][nt][1],
                                    acc[m][nt][2], acc[m][nt][3]);
        }
        __syncthreads();

        if (kq == 0) {
            #pragma unroll
            for (int peer = 0; peer < 3; peer++) {
                const float* slot = sEx + ((nh * 3 + peer) * 32 + lane) * EXR;
                #pragma unroll
                for (int m = 0; m < 2; m++)
                    #pragma unroll
                    for (int nt = 0; nt < 4; nt++) {
                        float4 p = *(const float4*)(slot + (m * 4 + nt) * 4);
                        acc[m][nt][0] += p.x; acc[m][nt][1] += p.y;
                        acc[m][nt][2] += p.z; acc[m][nt][3] += p.w;
                    }
            }
            // epilogue: tanh + W2-dot -> partial over this nh's 32 cols
            #pragma unroll
            for (int m = 0; m < 2; m++) {
                const int rl = m * 16 + g;
                float p0 = 0.f, p1 = 0.f;
                #pragma unroll
                for (int nt = 0; nt < 4; nt++) {
                    const int c0 = nh * 32 + nt * 8 + 2 * q;
                    const float w0 = sW2[c0], w1 = sW2[c0 + 1];
                    const float bb0 = sB1[c0], bb1 = sB1[c0 + 1];
                    p0 += tanha(acc[m][nt][0] + bb0) * w0
                        + tanha(acc[m][nt][1] + bb1) * w1;
                    p1 += tanha(acc[m][nt][2] + bb0) * w0
                        + tanha(acc[m][nt][3] + bb1) * w1;
                }
                p0 += __shfl_xor_sync(0xffffffffu, p0, 1);
                p0 += __shfl_xor_sync(0xffffffffu, p0, 2);
                p1 += __shfl_xor_sync(0xffffffffu, p1, 1);
                p1 += __shfl_xor_sync(0xffffffffu, p1, 2);
                if (q == 0) {
                    sP[(rl)     * 2 + nh] = p0;
                    sP[(rl + 8) * 2 + nh] = p1;
                }
            }
        }
        __syncthreads();

        const int b     = tile >> 8;         // batch (TT/TILE = 256)
        const int blk32 = tile & 255;

        if (tid < TILE) {
            const float s = bb2 + sP[tid * 2] + sP[tid * 2 + 1];
            const float e = __expf(s);
            sE[tid] = e;
            d_e[b * TT + blk32 * TILE + tid] = e;
            // d_E for the two 16-token blocks: reduce e over 16-lane halves
            float d = e;
            d += __shfl_xor_sync(0xffffffffu, d, 1);
            d += __shfl_xor_sync(0xffffffffu, d, 2);
            d += __shfl_xor_sync(0xffffffffu, d, 4);
            d += __shfl_xor_sync(0xffffffffu, d, 8);
            if ((tid & 15) == 0)
                d_E[b * NB1 + blk32 * 2 + (tid >> 4)] = d;
        }
        __syncthreads();

        // --- blocksum via MMA: d_S[h, block] = sum_t x[t,h]*e_t ---
        // warp owns m-tiles (h ranges) mt = warp*2, warp*2+1.
        {
            float bs0[4] = {0.f, 0.f, 0.f, 0.f};
            float bs1[4] = {0.f, 0.f, 0.f, 0.f};
            const int h0 = warp * 32 + g;      // mt0 row for this thread
            #pragma unroll
            for (int s = 0; s < 4; s++) {      // ksteps of 8 tokens
                const int t0 = s * 8 + q, t1 = t0 + 4;
                const float e0 = sE[t0], e1 = sE[t1];
                const float eh0 = tf32r(e0), eh1 = tf32r(e1);
                const float el0 = e0 - eh0,  el1 = e1 - eh1;
                const bool sel = (g == (s >> 1));   // block = s/2 rides n=g
                const uint32_t bh0 = sel ? __float_as_uint(eh0) : 0u;
                const uint32_t bh1 = sel ? __float_as_uint(eh1) : 0u;
                const uint32_t bl0 = sel ? __float_as_uint(el0) : 0u;
                const uint32_t bl1 = sel ? __float_as_uint(el1) : 0u;
                // A = x^T fragments (rows = h, cols = tokens)
                uint32_t a0 = __float_as_uint(sX[t0 * SROWA + h0]);
                uint32_t a1 = __float_as_uint(sX[t0 * SROWA + h0 + 8]);
                uint32_t a2 = __float_as_uint(sX[t1 * SROWA + h0]);
                uint32_t a3 = __float_as_uint(sX[t1 * SROWA + h0 + 8]);
                MMA_TF32(bs0, a0, a1, a2, a3, bh0, bh1);
                MMA_TF32(bs0, a0, a1, a2, a3, bl0, bl1);
                uint32_t c0 = __float_as_uint(sX[t0 * SROWA + h0 + 16]);
                uint32_t c1 = __float_as_uint(sX[t0 * SROWA + h0 + 24]);
                uint32_t c2 = __float_as_uint(sX[t1 * SROWA + h0 + 16]);
                uint32_t c3 = __float_as_uint(sX[t1 * SROWA + h0 + 24]);
                MMA_TF32(bs1, c0, c1, c2, c3, bh0, bh1);
                MMA_TF32(bs1, c0, c1, c2, c3, bl0, bl1);
            }
            if (q == 0) {   // cols 0,1 = blocks 0,1
                const size_t bi0 = (size_t)(b * NB1 + blk32 * 2)     * HH;
                const size_t bi1 = (size_t)(b * NB1 + blk32 * 2 + 1) * HH;
                d_S[bi0 + h0]      = bs0[0];
                d_S[bi1 + h0]      = bs0[1];
                d_S[bi0 + h0 + 8]  = bs0[2];
                d_S[bi1 + h0 + 8]  = bs0[3];
                d_S[bi0 + h0 + 16] = bs1[0];
                d_S[bi1 + h0 + 16] = bs1[1];
                d_S[bi0 + h0 + 24] = bs1[2];
                d_S[bi1 + h0 + 24] = bs1[3];
            }
        }
    }
}

// Aggregate 16 fine blocks -> 1 superblock
__global__ void __launch_bounds__(256) pass_ab_kernel()
{
    const int sb  = blockIdx.x & (NSB - 1);
    const int b   = blockIdx.x >> 5;
    const int tid = threadIdx.x;

    const float* Sb = d_S + ((size_t)(b * NB1 + sb * 16)) * HH + tid;
    float s0 = 0.f, s1 = 0.f, s2 = 0.f, s3 = 0.f;
    #pragma unroll
    for (int i = 0; i < 16; i += 4) {
        s0 += Sb[(size_t)(i + 0) * HH];
        s1 += Sb[(size_t)(i + 1) * HH];
        s2 += Sb[(size_t)(i + 2) * HH];
        s3 += Sb[(size_t)(i + 3) * HH];
    }
    d_S2[(size_t)(b * NSB + sb) * HH + tid] = (s0 + s1) + (s2 + s3);
    if (tid == 0) {
        float e = 0.f;
        #pragma unroll
        for (int i = 0; i < 16; i++) e += d_E[b * NB1 + sb * 16 + i];
        d_E2[b * NSB + sb] = e;
    }
}

__global__ void __launch_bounds__(256) pass_b_kernel(
    const float* __restrict__ x,
    const int*   __restrict__ boundaries,
    const int*   __restrict__ slot_mask,
    float*       __restrict__ out)
{
    const int k   = blockIdx.x;
    const int b   = blockIdx.y;
    const int tid = threadIdx.x;     // h index

    const int sidx  = b * KSLOT + k;
    const int start = boundaries[sidx * 2];
    const int end   = boundaries[sidx * 2 + 1];
    const int mask  = slot_mask[sidx];

    float* o = out + (size_t)sidx * HH;
    if (mask <= 0 || start >= end) { o[tid] = 0.f; return; }

    const float* xb  = x    + (size_t)b * TT * HH;
    const float* eb  = d_e  + b * TT;
    const float* Sb1 = d_S  + (size_t)b * NB1 * HH;
    const float* Eb1 = d_E  + b * NB1;
    const float* Sb2 = d_S2 + (size_t)b * NSB * HH;
    const float* Eb2 = d_E2 + b * NSB;

    float acc = 0.f, den = 0.f;

    auto tokens = [&](int t0, int t1) {
        float ea = 0.f, ec = 0.f, da = 0.f, dc = 0.f;
        int t = t0;
        for (; t + 2 <= t1; t += 2) {
            const float e0 = eb[t], e1 = eb[t + 1];
            ea += e0 * xb[(size_t)(t)     * HH + tid]; da += e0;
            ec += e1 * xb[(size_t)(t + 1) * HH + tid]; dc += e1;
        }
        if (t < t1) { const float e = eb[t]; ea += e * xb[(size_t)t * HH + tid]; da += e; }
        acc += ea + ec; den += da + dc;
    };
    auto blocks = [&](int i0, int i1) {
        float a0 = 0.f, a1 = 0.f, d0 = 0.f, d1 = 0.f;
        int i = i0;
        for (; i + 2 <= i1; i += 2) {
            a0 += Sb1[(size_t)(i)     * HH + tid]; d0 += Eb1[i];
            a1 += Sb1[(size_t)(i + 1) * HH + tid]; d1 += Eb1[i + 1];
        }
        if (i < i1) { a0 += Sb1[(size_t)i * HH + tid]; d0 += Eb1[i]; }
        acc += a0 + a1; den += d0 + d1;
    };

    const int fb = (start + 15) >> 4;
    const int lb = end >> 4;

    if (fb >= lb) {
        tokens(start, end);
    } else {
        tokens(start, fb * 16);
        tokens(lb * 16, end);

        const int fs = (fb + 15) >> 4;
        const int ls = lb >> 4;
        if (fs >= ls) {
            blocks(fb, lb);
        } else {
            blocks(fb, fs * 16);
            blocks(ls * 16, lb);
            float a0 = 0.f, a1 = 0.f, a2 = 0.f, a3 = 0.f;
            float d0 = 0.f, d1 = 0.f, d2 = 0.f, d3 = 0.f;
            int i = fs;
            for (; i + 4 <= ls; i += 4) {
                a0 += Sb2[(size_t)(i + 0) * HH + tid]; d0 += Eb2[i + 0];
                a1 += Sb2[(size_t)(i + 1) * HH + tid]; d1 += Eb2[i + 1];
                a2 += Sb2[(size_t)(i + 2) * HH + tid]; d2 += Eb2[i + 2];
                a3 += Sb2[(size_t)(i + 3) * HH + tid]; d3 += Eb2[i + 3];
            }
            for (; i < ls; i++) { a0 += Sb2[(size_t)i * HH + tid]; d0 += Eb2[i]; }
            acc += (a0 + a1) + (a2 + a3);
            den += (d0 + d1) + (d2 + d3);
        }
    }

    o[tid] = acc / den;   // den > 0: end > start and all e_t > 0
}

extern "C" void kernel_launch(void* const* d_in, const int* in_sizes, int n_in,
                              void* d_out, int out_size)
{
    const float* x          = (const float*)d_in[0];
    const int*   boundaries = (const int*)d_in[1];
    const int*   slot_mask  = (const int*)d_in[2];
    const float* W1         = (const float*)d_in[3];
    const float* b1         = (const float*)d_in[4];
    const float* W2         = (const float*)d_in[5];
    const float* b2         = (const float*)d_in[6];
    float* out = (float*)d_out;

    cudaFuncSetAttribute(pass_a_kernel,
                         cudaFuncAttributeMaxDynamicSharedMemorySize,
                         SMEM_A_BYTES);

    pass_a_kernel<<<296, 256, SMEM_A_BYTES>>>(x, W1, b1, W2, b2);
    pass_ab_kernel<<<BATCH * NSB, 256>>>();
    pass_b_kernel<<<dim3(KSLOT, BATCH), 256>>>(x, boundaries, slot_mask, out);
}

// round 10
// speedup vs baseline: 1.3160x; 1.2869x over previous
#include <cuda_runtime.h>
#include <cuda_fp16.h>
#include <cstdint>

// Problem constants
#define BATCH 16
#define TT    8192
#define HH    256
#define HQ    64
#define KSLOT 128
#define TILE  32                        // tokens per tile
#define NT32  (BATCH * (TT / TILE))     // 4096 tiles
#define NB1   (TT / 16)                 // 512 fine blocks (16 tokens)
#define NSB   (TT / 256)                // 32 superblocks
#define XROW  132                       // 32-bit words per fp16 tile row (264 halves)
#define XT_WORDS (TILE * XROW)          // 4224
#define EXR   36                        // exchange slot stride (words)

// Scratch
__device__ float d_e [BATCH * TT];
__device__ float d_S [BATCH * NB1 * HH];
__device__ float d_E [BATCH * NB1];
__device__ float d_S2[BATCH * NSB * HH];
__device__ float d_E2[BATCH * NSB];

__device__ __forceinline__ float tanha(float x) {
    float r; asm("tanh.approx.f32 %0, %1;" : "=f"(r) : "f"(x)); return r;
}
__device__ __forceinline__ uint32_t h2u(__half2 h) {
    uint32_t u; *(__half2*)&u = h; return u;
}
#define MMA_F16(acc, a0, a1, a2, a3, b0, b1) \
    asm volatile( \
        "mma.sync.aligned.m16n8k16.row.col.f32.f16.f16.f32 " \
        "{%0,%1,%2,%3},{%4,%5,%6,%7},{%8,%9},{%0,%1,%2,%3};" \
        : "+f"((acc)[0]), "+f"((acc)[1]), "+f"((acc)[2]), "+f"((acc)[3]) \
        : "r"(a0), "r"(a1), "r"(a2), "r"(a3), "r"(b0), "r"(b1))

// smem (32-bit words): sX16[4224] | sEx[6*32*EXR] | sE[32] | sP[64] | sB1[64] | sW2[64]
#define SMEM_A_WORDS (XT_WORDS + 6 * 32 * EXR + 32 + 64 + 64 + 64)
#define SMEM_A_BYTES (SMEM_A_WORDS * 4)

__global__ void __launch_bounds__(256, 2) pass_a_kernel(
    const float* __restrict__ x,
    const float* __restrict__ W1,
    const float* __restrict__ b1,
    const float* __restrict__ W2,
    const float* __restrict__ b2)
{
    extern __shared__ float sm[];
    uint32_t* sXw = (uint32_t*)sm;               // fp16 tile as 32-bit words
    float* sEx = sm + XT_WORDS;
    float* sE  = sEx + 6 * 32 * EXR;
    float* sP  = sE + 32;
    float* sB1 = sP + 64;
    float* sW2 = sB1 + 64;

    const int tid  = threadIdx.x;
    const int warp = tid >> 5;           // 0..7
    const int lane = tid & 31;
    const int g    = lane >> 2;          // 0..7
    const int q    = lane & 3;           // 0..3
    const int kq   = warp & 3;           // K quarter: k in [kq*64, kq*64+64)
    const int nh   = warp >> 2;          // n half: cols [nh*32, nh*32+32)

    uint32_t smem_u32;
    { uint64_t t64; asm("cvta.to.shared.u64 %0, %1;" : "=l"(t64) : "l"(sm));
      smem_u32 = (uint32_t)t64; }

    if (tid < 64) { sB1[tid] = b1[tid]; sW2[tid] = W2[tid]; }

    // --- W1 register-resident fp16 B fragments: warp covers 64k x 32n ---
    // m16n8k16 pairing (verified in R1): b0 = k{2q,2q+1}, b1 = k{2q+8,2q+9}
    uint32_t Breg[4][4][2];
    #pragma unroll
    for (int kt = 0; kt < 4; kt++)
        #pragma unroll
        for (int nt = 0; nt < 4; nt++) {
            const int n  = nh * 32 + nt * 8 + g;
            const int k0 = kq * 64 + kt * 16;
            Breg[kt][nt][0] = h2u(__floats2half2_rn(
                W1[(k0 + 2 * q)     * HQ + n], W1[(k0 + 2 * q + 1) * HQ + n]));
            Breg[kt][nt][1] = h2u(__floats2half2_rn(
                W1[(k0 + 2 * q + 8) * HQ + n], W1[(k0 + 2 * q + 9) * HQ + n]));
        }
    const float bb2 = b2[0];

    // loader mapping: thread -> (token t = tid>>3, h = (tid&7)*4 + 32*s)
    const int lt = tid >> 3;
    const int lj = tid & 7;
    const uint32_t stw0 = (uint32_t)(lt * XROW + lj * 2);   // word base for STS

    float4 pf[8];
    int tile = blockIdx.x;
    {   // prefetch first tile into registers
        const float* src = x + (size_t)tile * (TILE * HH) + (size_t)lt * HH + lj * 4;
        #pragma unroll
        for (int s = 0; s < 8; s++) pf[s] = *(const float4*)(src + 32 * s);
    }

    for (; tile < NT32; tile += gridDim.x) {
        const int next = tile + gridDim.x;

        __syncthreads();   // prev tile fully consumed (blocksum reads done)

        // --- store held registers as fp16 tile ---
        #pragma unroll
        for (int s = 0; s < 8; s++) {
            const uint32_t u0 = h2u(__floats2half2_rn(pf[s].x, pf[s].y));
            const uint32_t u1 = h2u(__floats2half2_rn(pf[s].z, pf[s].w));
            asm volatile("st.shared.v2.b32 [%0], {%1, %2};"
                :: "r"(smem_u32 + (stw0 + 16u * s) * 4), "r"(u0), "r"(u1));
        }
        // --- prefetch next tile into registers (overlaps compute) ---
        if (next < NT32) {
            const float* src = x + (size_t)next * (TILE * HH) + (size_t)lt * HH + lj * 4;
            #pragma unroll
            for (int s = 0; s < 8; s++) pf[s] = *(const float4*)(src + 32 * s);
        }
        __syncthreads();   // tile visible

        // --- MMA: warp computes 32 tokens x 32 n-cols over its K quarter ---
        float acc[2][4][4];
        #pragma unroll
        for (int m = 0; m < 2; m++)
            #pragma unroll
            for (int nt = 0; nt < 4; nt++)
                #pragma unroll
                for (int i = 0; i < 4; i++) acc[m][nt][i] = 0.f;

        #pragma unroll
        for (int kt = 0; kt < 4; kt++) {
            const int kb = kq * 32 + kt * 8 + q;     // word index within row
            #pragma unroll
            for (int m = 0; m < 2; m++) {
                const int rl = m * 16 + g;
                const uint32_t a0 = sXw[(rl)     * XROW + kb];
                const uint32_t a1 = sXw[(rl + 8) * XROW + kb];
                const uint32_t a2 = sXw[(rl)     * XROW + kb + 4];
                const uint32_t a3 = sXw[(rl + 8) * XROW + kb + 4];
                #pragma unroll
                for (int nt = 0; nt < 4; nt++)
                    MMA_F16(acc[m][nt], a0, a1, a2, a3,
                            Breg[kt][nt][0], Breg[kt][nt][1]);
            }
        }

        // --- K-quarter exchange: kq=1..3 ship partials to kq=0 warps ---
        if (kq > 0) {
            float* slot = sEx + ((nh * 3 + (kq - 1)) * 32 + lane) * EXR;
            #pragma unroll
            for (int m = 0; m < 2; m++)
                #pragma unroll
                for (int nt = 0; nt < 4; nt++)
                    *(float4*)(slot + (m * 4 + nt) * 4) =
                        make_float4(acc[m][nt][0], acc[m][nt][1],
                                    acc[m][nt][2], acc[m][nt][3]);
        }
        __syncthreads();

        if (kq == 0) {
            #pragma unroll
            for (int peer = 0; peer < 3; peer++) {
                const float* slot = sEx + ((nh * 3 + peer) * 32 + lane) * EXR;
                #pragma unroll
                for (int m = 0; m < 2; m++)
                    #pragma unroll
                    for (int nt = 0; nt < 4; nt++) {
                        float4 p = *(const float4*)(slot + (m * 4 + nt) * 4);
                        acc[m][nt][0] += p.x; acc[m][nt][1] += p.y;
                        acc[m][nt][2] += p.z; acc[m][nt][3] += p.w;
                    }
            }
            // epilogue: tanh + W2-dot over this nh's 32 cols
            #pragma unroll
            for (int m = 0; m < 2; m++) {
                const int rl = m * 16 + g;
                float p0 = 0.f, p1 = 0.f;
                #pragma unroll
                for (int nt = 0; nt < 4; nt++) {
                    const int c0 = nh * 32 + nt * 8 + 2 * q;
                    const float w0 = sW2[c0], w1 = sW2[c0 + 1];
                    const float bb0 = sB1[c0], bb1 = sB1[c0 + 1];
                    p0 += tanha(acc[m][nt][0] + bb0) * w0
                        + tanha(acc[m][nt][1] + bb1) * w1;
                    p1 += tanha(acc[m][nt][2] + bb0) * w0
                        + tanha(acc[m][nt][3] + bb1) * w1;
                }
                p0 += __shfl_xor_sync(0xffffffffu, p0, 1);
                p0 += __shfl_xor_sync(0xffffffffu, p0, 2);
                p1 += __shfl_xor_sync(0xffffffffu, p1, 1);
                p1 += __shfl_xor_sync(0xffffffffu, p1, 2);
                if (q == 0) {
                    sP[(rl)     * 2 + nh] = p0;
                    sP[(rl + 8) * 2 + nh] = p1;
                }
            }
        }
        __syncthreads();

        const int b     = tile >> 8;         // batch (TT/TILE = 256)
        const int blk32 = tile & 255;

        if (tid < TILE) {
            const float s = bb2 + sP[tid * 2] + sP[tid * 2 + 1];
            const float e = __expf(s);
            sE[tid] = e;
            d_e[b * TT + blk32 * TILE + tid] = e;
            float d = e;
            d += __shfl_xor_sync(0xffffffffu, d, 1);
            d += __shfl_xor_sync(0xffffffffu, d, 2);
            d += __shfl_xor_sync(0xffffffffu, d, 4);
            d += __shfl_xor_sync(0xffffffffu, d, 8);
            if ((tid & 15) == 0)
                d_E[b * NB1 + blk32 * 2 + (tid >> 4)] = d;
        }
        __syncthreads();   // sE visible

        // --- blocksum: thread = (block j, h-pair), half2 loads ---
        {
            const int jb = tid >> 7;         // 0,1 -> 16-token block
            const int hp = tid & 127;        // h pair index (h = 2*hp)
            float ax = 0.f, ay = 0.f;
            #pragma unroll
            for (int t = 0; t < 16; t++) {
                const int tt = jb * 16 + t;
                const uint32_t v = sXw[tt * XROW + hp];
                const float2 f = __half22float2(*(const __half2*)&v);
                const float e = sE[tt];
                ax += e * f.x; ay += e * f.y;
            }
            const int bi = b * NB1 + blk32 * 2 + jb;
            *(float2*)&d_S[(size_t)bi * HH + 2 * hp] = make_float2(ax, ay);
        }
    }
}

// Aggregate 16 fine blocks -> 1 superblock
__global__ void __launch_bounds__(256) pass_ab_kernel()
{
    const int sb  = blockIdx.x & (NSB - 1);
    const int b   = blockIdx.x >> 5;
    const int tid = threadIdx.x;

    const float* Sb = d_S + ((size_t)(b * NB1 + sb * 16)) * HH + tid;
    float s0 = 0.f, s1 = 0.f, s2 = 0.f, s3 = 0.f;
    #pragma unroll
    for (int i = 0; i < 16; i += 4) {
        s0 += Sb[(size_t)(i + 0) * HH];
        s1 += Sb[(size_t)(i + 1) * HH];
        s2 += Sb[(size_t)(i + 2) * HH];
        s3 += Sb[(size_t)(i + 3) * HH];
    }
    d_S2[(size_t)(b * NSB + sb) * HH + tid] = (s0 + s1) + (s2 + s3);
    if (tid == 0) {
        float e = 0.f;
        #pragma unroll
        for (int i = 0; i < 16; i++) e += d_E[b * NB1 + sb * 16 + i];
        d_E2[b * NSB + sb] = e;
    }
}

__global__ void __launch_bounds__(256) pass_b_kernel(
    const float* __restrict__ x,
    const int*   __restrict__ boundaries,
    const int*   __restrict__ slot_mask,
    float*       __restrict__ out)
{
    const int k   = blockIdx.x;
    const int b   = blockIdx.y;
    const int tid = threadIdx.x;     // h index

    const int sidx  = b * KSLOT + k;
    const int start = boundaries[sidx * 2];
    const int end   = boundaries[sidx * 2 + 1];
    const int mask  = slot_mask[sidx];

    float* o = out + (size_t)sidx * HH;
    if (mask <= 0 || start >= end) { o[tid] = 0.f; return; }

    const float* xb  = x    + (size_t)b * TT * HH;
    const float* eb  = d_e  + b * TT;
    const float* Sb1 = d_S  + (size_t)b * NB1 * HH;
    const float* Eb1 = d_E  + b * NB1;
    const float* Sb2 = d_S2 + (size_t)b * NSB * HH;
    const float* Eb2 = d_E2 + b * NSB;

    float acc = 0.f, den = 0.f;

    auto tokens = [&](int t0, int t1) {
        float ea = 0.f, ec = 0.f, da = 0.f, dc = 0.f;
        int t = t0;
        for (; t + 2 <= t1; t += 2) {
            const float e0 = eb[t], e1 = eb[t + 1];
            ea += e0 * xb[(size_t)(t)     * HH + tid]; da += e0;
            ec += e1 * xb[(size_t)(t + 1) * HH + tid]; dc += e1;
        }
        if (t < t1) { const float e = eb[t]; ea += e * xb[(size_t)t * HH + tid]; da += e; }
        acc += ea + ec; den += da + dc;
    };
    auto blocks = [&](int i0, int i1) {
        float a0 = 0.f, a1 = 0.f, d0 = 0.f, d1 = 0.f;
        int i = i0;
        for (; i + 2 <= i1; i += 2) {
            a0 += Sb1[(size_t)(i)     * HH + tid]; d0 += Eb1[i];
            a1 += Sb1[(size_t)(i + 1) * HH + tid]; d1 += Eb1[i + 1];
        }
        if (i < i1) { a0 += Sb1[(size_t)i * HH + tid]; d0 += Eb1[i]; }
        acc += a0 + a1; den += d0 + d1;
    };

    const int fb = (start + 15) >> 4;
    const int lb = end >> 4;

    if (fb >= lb) {
        tokens(start, end);
    } else {
        tokens(start, fb * 16);
        tokens(lb * 16, end);

        const int fs = (fb + 15) >> 4;
        const int ls = lb >> 4;
        if (fs >= ls) {
            blocks(fb, lb);
        } else {
            blocks(fb, fs * 16);
            blocks(ls * 16, lb);
            float a0 = 0.f, a1 = 0.f, a2 = 0.f, a3 = 0.f;
            float d0 = 0.f, d1 = 0.f, d2 = 0.f, d3 = 0.f;
            int i = fs;
            for (; i + 4 <= ls; i += 4) {
                a0 += Sb2[(size_t)(i + 0) * HH + tid]; d0 += Eb2[i + 0];
                a1 += Sb2[(size_t)(i + 1) * HH + tid]; d1 += Eb2[i + 1];
                a2 += Sb2[(size_t)(i + 2) * HH + tid]; d2 += Eb2[i + 2];
                a3 += Sb2[(size_t)(i + 3) * HH + tid]; d3 += Eb2[i + 3];
            }
            for (; i < ls; i++) { a0 += Sb2[(size_t)i * HH + tid]; d0 += Eb2[i]; }
            acc += (a0 + a1) + (a2 + a3);
            den += (d0 + d1) + (d2 + d3);
        }
    }

    o[tid] = acc / den;   // den > 0: end > start and all e_t > 0
}

extern "C" void kernel_launch(void* const* d_in, const int* in_sizes, int n_in,
                              void* d_out, int out_size)
{
    const float* x          = (const float*)d_in[0];
    const int*   boundaries = (const int*)d_in[1];
    const int*   slot_mask  = (const int*)d_in[2];
    const float* W1         = (const float*)d_in[3];
    const float* b1         = (const float*)d_in[4];
    const float* W2         = (const float*)d_in[5];
    const float* b2         = (const float*)d_in[6];
    float* out = (float*)d_out;

    cudaFuncSetAttribute(pass_a_kernel,
                         cudaFuncAttributeMaxDynamicSharedMemorySize,
                         SMEM_A_BYTES);

    pass_a_kernel<<<296, 256, SMEM_A_BYTES>>>(x, W1, b1, W2, b2);
    pass_ab_kernel<<<BATCH * NSB, 256>>>();
    pass_b_kernel<<<dim3(KSLOT, BATCH), 256>>>(x, boundaries, slot_mask, out);
}

// round 11
// speedup vs baseline: 1.4365x; 1.0915x over previous
#include <cuda_runtime.h>
#include <cuda_fp16.h>
#include <cstdint>

// Problem constants
#define BATCH 16
#define TT    8192
#define HH    256
#define HQ    64
#define KSLOT 128
#define TILE  32                        // tokens per tile
#define NT32  (BATCH * (TT / TILE))     // 4096 tiles
#define NB1   (TT / 16)                 // 512 fine blocks (16 tokens)
#define NSB   (TT / 256)                // 32 superblocks
#define XROW  132                       // 32-bit words per fp16 tile row (264 halves)
#define XT_WORDS (TILE * XROW)          // 4224

// Scratch
__device__ float d_e [BATCH * TT];
__device__ float d_S [BATCH * NB1 * HH];
__device__ float d_E [BATCH * NB1];
__device__ float d_S2[BATCH * NSB * HH];
__device__ float d_E2[BATCH * NSB];

__device__ __forceinline__ float tanha(float x) {
    float r; asm("tanh.approx.f32 %0, %1;" : "=f"(r) : "f"(x)); return r;
}
__device__ __forceinline__ uint32_t h2u(__half2 h) {
    uint32_t u; *(__half2*)&u = h; return u;
}
#define MMA_F16(acc, a0, a1, a2, a3, b0, b1) \
    asm volatile( \
        "mma.sync.aligned.m16n8k16.row.col.f32.f16.f16.f32 " \
        "{%0,%1,%2,%3},{%4,%5,%6,%7},{%8,%9},{%0,%1,%2,%3};" \
        : "+f"((acc)[0]), "+f"((acc)[1]), "+f"((acc)[2]), "+f"((acc)[3]) \
        : "r"(a0), "r"(a1), "r"(a2), "r"(a3), "r"(b0), "r"(b1))

// smem (32-bit words): sX16[4224] | sP[32*4+16] | sE[32] | sB1[64] | sW2[64]
#define SMEM_A_WORDS (XT_WORDS + 32 * 4 + 16 + 32 + 64 + 64)
#define SMEM_A_BYTES (SMEM_A_WORDS * 4)

__global__ void __launch_bounds__(256, 2) pass_a_kernel(
    const float* __restrict__ x,
    const float* __restrict__ W1,
    const float* __restrict__ b1,
    const float* __restrict__ W2,
    const float* __restrict__ b2)
{
    extern __shared__ float sm[];
    uint32_t* sXw = (uint32_t*)sm;               // fp16 tile as 32-bit words
    float* sP  = sm + XT_WORDS;                  // [32][4] + pad
    float* sE  = sP + 32 * 4 + 16;
    float* sB1 = sE + 32;
    float* sW2 = sB1 + 64;

    const int tid  = threadIdx.x;
    const int warp = tid >> 5;           // 0..7
    const int lane = tid & 31;
    const int g    = lane >> 2;          // 0..7
    const int q    = lane & 3;           // 0..3
    const int th   = warp & 1;           // token half: rows [th*16, th*16+16)
    const int nq   = warp >> 1;          // n quarter: cols [nq*16, nq*16+16)
    const int r0   = th * 16;            // warp's token base

    uint32_t smem_u32;
    { uint64_t t64; asm("cvta.to.shared.u64 %0, %1;" : "=l"(t64) : "l"(sm));
      smem_u32 = (uint32_t)t64; }

    if (tid < 64) { sB1[tid] = b1[tid]; sW2[tid] = W2[tid]; }

    // --- W1 register-resident fp16 B frags: warp covers FULL K=256 x 16 n ---
    // m16n8k16: b0 = k{2q,2q+1}, b1 = k{2q+8,2q+9} (verified layout)
    uint32_t Breg[16][2][2];
    #pragma unroll
    for (int kt = 0; kt < 16; kt++)
        #pragma unroll
        for (int nt = 0; nt < 2; nt++) {
            const int n  = nq * 16 + nt * 8 + g;
            const int k0 = kt * 16;
            Breg[kt][nt][0] = h2u(__floats2half2_rn(
                W1[(k0 + 2 * q)     * HQ + n], W1[(k0 + 2 * q + 1) * HQ + n]));
            Breg[kt][nt][1] = h2u(__floats2half2_rn(
                W1[(k0 + 2 * q + 8) * HQ + n], W1[(k0 + 2 * q + 9) * HQ + n]));
        }
    const float bb2 = b2[0];

    // loader mapping: thread -> (token t = tid>>3, h = (tid&7)*4 + 32*s)
    const int lt = tid >> 3;
    const int lj = tid & 7;
    const uint32_t stw0 = (uint32_t)(lt * XROW + lj * 2);

    float4 pf[8];
    int tile = blockIdx.x;
    {   // prefetch first tile into registers
        const float* src = x + (size_t)tile * (TILE * HH) + (size_t)lt * HH + lj * 4;
        #pragma unroll
        for (int s = 0; s < 8; s++) pf[s] = *(const float4*)(src + 32 * s);
    }

    for (; tile < NT32; tile += gridDim.x) {
        const int next = tile + gridDim.x;

        __syncthreads();   // prev tile fully consumed

        // --- store held registers as fp16 tile ---
        #pragma unroll
        for (int s = 0; s < 8; s++) {
            const uint32_t u0 = h2u(__floats2half2_rn(pf[s].x, pf[s].y));
            const uint32_t u1 = h2u(__floats2half2_rn(pf[s].z, pf[s].w));
            asm volatile("st.shared.v2.b32 [%0], {%1, %2};"
                :: "r"(smem_u32 + (stw0 + 16u * s) * 4), "r"(u0), "r"(u1));
        }
        // --- prefetch next tile (overlaps compute) ---
        if (next < NT32) {
            const float* src = x + (size_t)next * (TILE * HH) + (size_t)lt * HH + lj * 4;
            #pragma unroll
            for (int s = 0; s < 8; s++) pf[s] = *(const float4*)(src + 32 * s);
        }
        __syncthreads();   // tile visible

        // --- MMA: warp = 16 tokens x 16 n-cols x full K (32 HMMA) ---
        float acc[2][4];
        #pragma unroll
        for (int nt = 0; nt < 2; nt++)
            #pragma unroll
            for (int i = 0; i < 4; i++) acc[nt][i] = 0.f;

        #pragma unroll
        for (int kt = 0; kt < 16; kt++) {
            const int kb = kt * 8 + q;           // word index within row
            const uint32_t a0 = sXw[(r0 + g)     * XROW + kb];
            const uint32_t a1 = sXw[(r0 + g + 8) * XROW + kb];
            const uint32_t a2 = sXw[(r0 + g)     * XROW + kb + 4];
            const uint32_t a3 = sXw[(r0 + g + 8) * XROW + kb + 4];
            #pragma unroll
            for (int nt = 0; nt < 2; nt++)
                MMA_F16(acc[nt], a0, a1, a2, a3,
                        Breg[kt][nt][0], Breg[kt][nt][1]);
        }

        // --- local epilogue: tanh + W2-dot over this warp's 16 cols ---
        {
            float p0 = 0.f, p1 = 0.f;
            #pragma unroll
            for (int nt = 0; nt < 2; nt++) {
                const int c0 = nq * 16 + nt * 8 + 2 * q;
                const float w0 = sW2[c0], w1 = sW2[c0 + 1];
                const float bb0 = sB1[c0], bb1 = sB1[c0 + 1];
                p0 += tanha(acc[nt][0] + bb0) * w0
                    + tanha(acc[nt][1] + bb1) * w1;
                p1 += tanha(acc[nt][2] + bb0) * w0
                    + tanha(acc[nt][3] + bb1) * w1;
            }
            p0 += __shfl_xor_sync(0xffffffffu, p0, 1);
            p0 += __shfl_xor_sync(0xffffffffu, p0, 2);
            p1 += __shfl_xor_sync(0xffffffffu, p1, 1);
            p1 += __shfl_xor_sync(0xffffffffu, p1, 2);
            if (q == 0) {
                sP[(r0 + g)     * 4 + nq] = p0;
                sP[(r0 + g + 8) * 4 + nq] = p1;
            }
        }
        __syncthreads();

        const int b     = tile >> 8;         // batch (TT/TILE = 256)
        const int blk32 = tile & 255;

        if (tid < TILE) {
            const float s = bb2 + sP[tid * 4] + sP[tid * 4 + 1]
                                + sP[tid * 4 + 2] + sP[tid * 4 + 3];
            const float e = __expf(s);
            sE[tid] = e;
            d_e[b * TT + blk32 * TILE + tid] = e;
            float d = e;
            d += __shfl_xor_sync(0xffffffffu, d, 1);
            d += __shfl_xor_sync(0xffffffffu, d, 2);
            d += __shfl_xor_sync(0xffffffffu, d, 4);
            d += __shfl_xor_sync(0xffffffffu, d, 8);
            if ((tid & 15) == 0)
                d_E[b * NB1 + blk32 * 2 + (tid >> 4)] = d;
        }
        __syncthreads();   // sE visible

        // --- blocksum: thread = (block j, h-pair), half2 loads ---
        {
            const int jb = tid >> 7;         // 0,1 -> 16-token block
            const int hp = tid & 127;        // h pair index (h = 2*hp)
            float ax = 0.f, ay = 0.f;
            #pragma unroll
            for (int t = 0; t < 16; t++) {
                const int tt = jb * 16 + t;
                const uint32_t v = sXw[tt * XROW + hp];
                const float2 f = __half22float2(*(const __half2*)&v);
                const float e = sE[tt];
                ax += e * f.x; ay += e * f.y;
            }
            const int bi = b * NB1 + blk32 * 2 + jb;
            *(float2*)&d_S[(size_t)bi * HH + 2 * hp] = make_float2(ax, ay);
        }
    }
}

// Aggregate 16 fine blocks -> 1 superblock
__global__ void __launch_bounds__(256) pass_ab_kernel()
{
    const int sb  = blockIdx.x & (NSB - 1);
    const int b   = blockIdx.x >> 5;
    const int tid = threadIdx.x;

    const float* Sb = d_S + ((size_t)(b * NB1 + sb * 16)) * HH + tid;
    float s0 = 0.f, s1 = 0.f, s2 = 0.f, s3 = 0.f;
    #pragma unroll
    for (int i = 0; i < 16; i += 4) {
        s0 += Sb[(size_t)(i + 0) * HH];
        s1 += Sb[(size_t)(i + 1) * HH];
        s2 += Sb[(size_t)(i + 2) * HH];
        s3 += Sb[(size_t)(i + 3) * HH];
    }
    d_S2[(size_t)(b * NSB + sb) * HH + tid] = (s0 + s1) + (s2 + s3);
    if (tid == 0) {
        float e = 0.f;
        #pragma unroll
        for (int i = 0; i < 16; i++) e += d_E[b * NB1 + sb * 16 + i];
        d_E2[b * NSB + sb] = e;
    }
}

__global__ void __launch_bounds__(256) pass_b_kernel(
    const float* __restrict__ x,
    const int*   __restrict__ boundaries,
    const int*   __restrict__ slot_mask,
    float*       __restrict__ out)
{
    const int k   = blockIdx.x;
    const int b   = blockIdx.y;
    const int tid = threadIdx.x;     // h index

    const int sidx  = b * KSLOT + k;
    const int start = boundaries[sidx * 2];
    const int end   = boundaries[sidx * 2 + 1];
    const int mask  = slot_mask[sidx];

    float* o = out + (size_t)sidx * HH;
    if (mask <= 0 || start >= end) { o[tid] = 0.f; return; }

    const float* xb  = x    + (size_t)b * TT * HH;
    const float* eb  = d_e  + b * TT;
    const float* Sb1 = d_S  + (size_t)b * NB1 * HH;
    const float* Eb1 = d_E  + b * NB1;
    const float* Sb2 = d_S2 + (size_t)b * NSB * HH;
    const float* Eb2 = d_E2 + b * NSB;

    float acc = 0.f, den = 0.f;

    auto tokens = [&](int t0, int t1) {
        float ea = 0.f, ec = 0.f, da = 0.f, dc = 0.f;
        int t = t0;
        for (; t + 2 <= t1; t += 2) {
            const float e0 = eb[t], e1 = eb[t + 1];
            ea += e0 * xb[(size_t)(t)     * HH + tid]; da += e0;
            ec += e1 * xb[(size_t)(t + 1) * HH + tid]; dc += e1;
        }
        if (t < t1) { const float e = eb[t]; ea += e * xb[(size_t)t * HH + tid]; da += e; }
        acc += ea + ec; den += da + dc;
    };
    auto blocks = [&](int i0, int i1) {
        float a0 = 0.f, a1 = 0.f, d0 = 0.f, d1 = 0.f;
        int i = i0;
        for (; i + 2 <= i1; i += 2) {
            a0 += Sb1[(size_t)(i)     * HH + tid]; d0 += Eb1[i];
            a1 += Sb1[(size_t)(i + 1) * HH + tid]; d1 += Eb1[i + 1];
        }
        if (i < i1) { a0 += Sb1[(size_t)i * HH + tid]; d0 += Eb1[i]; }
        acc += a0 + a1; den += d0 + d1;
    };

    const int fb = (start + 15) >> 4;
    const int lb = end >> 4;

    if (fb >= lb) {
        tokens(start, end);
    } else {
        tokens(start, fb * 16);
        tokens(lb * 16, end);

        const int fs = (fb + 15) >> 4;
        const int ls = lb >> 4;
        if (fs >= ls) {
            blocks(fb, lb);
        } else {
            blocks(fb, fs * 16);
            blocks(ls * 16, lb);
            float a0 = 0.f, a1 = 0.f, a2 = 0.f, a3 = 0.f;
            float d0 = 0.f, d1 = 0.f, d2 = 0.f, d3 = 0.f;
            int i = fs;
            for (; i + 4 <= ls; i += 4) {
                a0 += Sb2[(size_t)(i + 0) * HH + tid]; d0 += Eb2[i + 0];
                a1 += Sb2[(size_t)(i + 1) * HH + tid]; d1 += Eb2[i + 1];
                a2 += Sb2[(size_t)(i + 2) * HH + tid]; d2 += Eb2[i + 2];
                a3 += Sb2[(size_t)(i + 3) * HH + tid]; d3 += Eb2[i + 3];
            }
            for (; i < ls; i++) { a0 += Sb2[(size_t)i * HH + tid]; d0 += Eb2[i]; }
            acc += (a0 + a1) + (a2 + a3);
            den += (d0 + d1) + (d2 + d3);
        }
    }

    o[tid] = acc / den;   // den > 0: end > start and all e_t > 0
}

extern "C" void kernel_launch(void* const* d_in, const int* in_sizes, int n_in,
                              void* d_out, int out_size)
{
    const float* x          = (const float*)d_in[0];
    const int*   boundaries = (const int*)d_in[1];
    const int*   slot_mask  = (const int*)d_in[2];
    const float* W1         = (const float*)d_in[3];
    const float* b1         = (const float*)d_in[4];
    const float* W2         = (const float*)d_in[5];
    const float* b2         = (const float*)d_in[6];
    float* out = (float*)d_out;

    cudaFuncSetAttribute(pass_a_kernel,
                         cudaFuncAttributeMaxDynamicSharedMemorySize,
                         SMEM_A_BYTES);

    pass_a_kernel<<<296, 256, SMEM_A_BYTES>>>(x, W1, b1, W2, b2);
    pass_ab_kernel<<<BATCH * NSB, 256>>>();
    pass_b_kernel<<<dim3(KSLOT, BATCH), 256>>>(x, boundaries, slot_mask, out);
}

// round 12
// speedup vs baseline: 1.5504x; 1.0793x over previous
#include <cuda_runtime.h>
#include <cuda_fp16.h>
#include <cstdint>

// Problem constants
#define BATCH 16
#define TT    8192
#define HH    256
#define HQ    64
#define KSLOT 128
#define TILE  32                        // tokens per tile
#define NT32  (BATCH * (TT / TILE))     // 4096 tiles
#define NB1   (TT / 16)                 // 512 fine blocks (16 tokens)
#define NSB   (TT / 256)                // 32 superblocks
#define XROW  132                       // 32-bit words per fp16 tile row (264 halves)
#define XT_WORDS (TILE * XROW)          // 4224

// Scratch
__device__ float d_e [BATCH * TT];
__device__ float d_S [BATCH * NB1 * HH];
__device__ float d_E [BATCH * NB1];
__device__ float d_S2[BATCH * NSB * HH];
__device__ float d_E2[BATCH * NSB];

__device__ __forceinline__ float tanha(float x) {
    float r; asm("tanh.approx.f32 %0, %1;" : "=f"(r) : "f"(x)); return r;
}
__device__ __forceinline__ uint32_t h2u(__half2 h) {
    uint32_t u; *(__half2*)&u = h; return u;
}
#define MMA_F16(acc, a0, a1, a2, a3, b0, b1) \
    asm volatile( \
        "mma.sync.aligned.m16n8k16.row.col.f32.f16.f16.f32 " \
        "{%0,%1,%2,%3},{%4,%5,%6,%7},{%8,%9},{%0,%1,%2,%3};" \
        : "+f"((acc)[0]), "+f"((acc)[1]), "+f"((acc)[2]), "+f"((acc)[3]) \
        : "r"(a0), "r"(a1), "r"(a2), "r"(a3), "r"(b0), "r"(b1))

// smem (32-bit words): sX16[4224] | sP[32*4+16] | sE[32] | sB1[64] | sW2[64]
#define SMEM_A_WORDS (XT_WORDS + 32 * 4 + 16 + 32 + 64 + 64)
#define SMEM_A_BYTES (SMEM_A_WORDS * 4)

__global__ void __launch_bounds__(256, 2) pass_a_kernel(
    const float* __restrict__ x,
    const float* __restrict__ W1,
    const float* __restrict__ b1,
    const float* __restrict__ W2,
    const float* __restrict__ b2)
{
    extern __shared__ float sm[];
    uint32_t* sXw = (uint32_t*)sm;               // fp16 tile as 32-bit words
    float* sP  = sm + XT_WORDS;                  // [32][4] + pad
    float* sE  = sP + 32 * 4 + 16;
    float* sB1 = sE + 32;
    float* sW2 = sB1 + 64;

    const int tid  = threadIdx.x;
    const int warp = tid >> 5;           // 0..7
    const int lane = tid & 31;
    const int g    = lane >> 2;          // 0..7
    const int q    = lane & 3;           // 0..3
    const int th   = warp & 1;           // token half: rows [th*16, th*16+16)
    const int nq   = warp >> 1;          // n quarter: cols [nq*16, nq*16+16)
    const int r0   = th * 16;            // warp's token base

    uint32_t smem_u32;
    { uint64_t t64; asm("cvta.to.shared.u64 %0, %1;" : "=l"(t64) : "l"(sm));
      smem_u32 = (uint32_t)t64; }

    if (tid < 64) { sB1[tid] = b1[tid]; sW2[tid] = W2[tid]; }

    // --- W1 register-resident fp16 B frags: warp covers FULL K=256 x 16 n ---
    uint32_t Breg[16][2][2];
    #pragma unroll
    for (int kt = 0; kt < 16; kt++)
        #pragma unroll
        for (int nt = 0; nt < 2; nt++) {
            const int n  = nq * 16 + nt * 8 + g;
            const int k0 = kt * 16;
            Breg[kt][nt][0] = h2u(__floats2half2_rn(
                W1[(k0 + 2 * q)     * HQ + n], W1[(k0 + 2 * q + 1) * HQ + n]));
            Breg[kt][nt][1] = h2u(__floats2half2_rn(
                W1[(k0 + 2 * q + 8) * HQ + n], W1[(k0 + 2 * q + 9) * HQ + n]));
        }
    const float bb2 = b2[0];

    // ldmatrix base: lane -> row r0+(lane&15), byte-col (lane&16)
    const uint32_t lmbase = smem_u32
        + (uint32_t)(r0 + (lane & 15)) * (XROW * 4u)
        + (uint32_t)(lane & 16);

    // loader mapping: thread -> (token t = tid>>3, h = (tid&7)*4 + 32*s)
    const int lt = tid >> 3;
    const int lj = tid & 7;
    const uint32_t stw0 = (uint32_t)(lt * XROW + lj * 2);

    float4 pf[8];
    int tile = blockIdx.x;
    {   // prefetch first tile into registers
        const float* src = x + (size_t)tile * (TILE * HH) + (size_t)lt * HH + lj * 4;
        #pragma unroll
        for (int s = 0; s < 8; s++) pf[s] = *(const float4*)(src + 32 * s);
    }

    for (; tile < NT32; tile += gridDim.x) {
        const int next = tile + gridDim.x;

        __syncthreads();   // prev tile fully consumed

        // --- store held registers as fp16 tile ---
        #pragma unroll
        for (int s = 0; s < 8; s++) {
            const uint32_t u0 = h2u(__floats2half2_rn(pf[s].x, pf[s].y));
            const uint32_t u1 = h2u(__floats2half2_rn(pf[s].z, pf[s].w));
            asm volatile("st.shared.v2.b32 [%0], {%1, %2};"
                :: "r"(smem_u32 + (stw0 + 16u * s) * 4), "r"(u0), "r"(u1));
        }
        // --- prefetch next tile (overlaps compute) ---
        if (next < NT32) {
            const float* src = x + (size_t)next * (TILE * HH) + (size_t)lt * HH + lj * 4;
            #pragma unroll
            for (int s = 0; s < 8; s++) pf[s] = *(const float4*)(src + 32 * s);
        }
        __syncthreads();   // tile visible

        // --- MMA: warp = 16 tokens x 16 n-cols x full K (16 LDSM + 32 HMMA) ---
        float acc[2][4];
        #pragma unroll
        for (int nt = 0; nt < 2; nt++)
            #pragma unroll
            for (int i = 0; i < 4; i++) acc[nt][i] = 0.f;

        #pragma unroll
        for (int kt = 0; kt < 16; kt++) {
            uint32_t a0, a1, a2, a3;
            asm volatile(
                "ldmatrix.sync.aligned.m8n8.x4.shared.b16 {%0,%1,%2,%3}, [%4];"
                : "=r"(a0), "=r"(a1), "=r"(a2), "=r"(a3)
                : "r"(lmbase + (uint32_t)(kt * 32)));
            #pragma unroll
            for (int nt = 0; nt < 2; nt++)
                MMA_F16(acc[nt], a0, a1, a2, a3,
                        Breg[kt][nt][0], Breg[kt][nt][1]);
        }

        // --- local epilogue: tanh + W2-dot over this warp's 16 cols ---
        {
            float p0 = 0.f, p1 = 0.f;
            #pragma unroll
            for (int nt = 0; nt < 2; nt++) {
                const int c0 = nq * 16 + nt * 8 + 2 * q;
                const float w0 = sW2[c0], w1 = sW2[c0 + 1];
                const float bb0 = sB1[c0], bb1 = sB1[c0 + 1];
                p0 += tanha(acc[nt][0] + bb0) * w0
                    + tanha(acc[nt][1] + bb1) * w1;
                p1 += tanha(acc[nt][2] + bb0) * w0
                    + tanha(acc[nt][3] + bb1) * w1;
            }
            p0 += __shfl_xor_sync(0xffffffffu, p0, 1);
            p0 += __shfl_xor_sync(0xffffffffu, p0, 2);
            p1 += __shfl_xor_sync(0xffffffffu, p1, 1);
            p1 += __shfl_xor_sync(0xffffffffu, p1, 2);
            if (q == 0) {
                sP[(r0 + g)     * 4 + nq] = p0;
                sP[(r0 + g + 8) * 4 + nq] = p1;
            }
        }
        __syncthreads();

        const int b     = tile >> 8;         // batch (TT/TILE = 256)
        const int blk32 = tile & 255;

        if (tid < TILE) {
            const float4 p4 = *(const float4*)&sP[tid * 4];
            const float s = bb2 + (p4.x + p4.y) + (p4.z + p4.w);
            const float e = __expf(s);
            sE[tid] = e;
            d_e[b * TT + blk32 * TILE + tid] = e;
            float d = e;
            d += __shfl_xor_sync(0xffffffffu, d, 1);
            d += __shfl_xor_sync(0xffffffffu, d, 2);
            d += __shfl_xor_sync(0xffffffffu, d, 4);
            d += __shfl_xor_sync(0xffffffffu, d, 8);
            if ((tid & 15) == 0)
                d_E[b * NB1 + blk32 * 2 + (tid >> 4)] = d;
        }
        __syncthreads();   // sE visible

        // --- blocksum: thread = (block j, h-pair), half2 loads ---
        {
            const int jb = tid >> 7;         // 0,1 -> 16-token block
            const int hp = tid & 127;        // h pair index (h = 2*hp)
            float ax = 0.f, ay = 0.f;
            #pragma unroll
            for (int t = 0; t < 16; t++) {
                const int tt = jb * 16 + t;
                const uint32_t v = sXw[tt * XROW + hp];
                const float2 f = __half22float2(*(const __half2*)&v);
                const float e = sE[tt];
                ax += e * f.x; ay += e * f.y;
            }
            const int bi = b * NB1 + blk32 * 2 + jb;
            *(float2*)&d_S[(size_t)bi * HH + 2 * hp] = make_float2(ax, ay);
        }
    }
}

// Aggregate 16 fine blocks -> 1 superblock
__global__ void __launch_bounds__(256) pass_ab_kernel()
{
    const int sb  = blockIdx.x & (NSB - 1);
    const int b   = blockIdx.x >> 5;
    const int tid = threadIdx.x;

    const float* Sb = d_S + ((size_t)(b * NB1 + sb * 16)) * HH + tid;
    float s0 = 0.f, s1 = 0.f, s2 = 0.f, s3 = 0.f;
    #pragma unroll
    for (int i = 0; i < 16; i += 4) {
        s0 += Sb[(size_t)(i + 0) * HH];
        s1 += Sb[(size_t)(i + 1) * HH];
        s2 += Sb[(size_t)(i + 2) * HH];
        s3 += Sb[(size_t)(i + 3) * HH];
    }
    d_S2[(size_t)(b * NSB + sb) * HH + tid] = (s0 + s1) + (s2 + s3);
    if (tid == 0) {
        float e = 0.f;
        #pragma unroll
        for (int i = 0; i < 16; i++) e += d_E[b * NB1 + sb * 16 + i];
        d_E2[b * NSB + sb] = e;
    }
}

__global__ void __launch_bounds__(256) pass_b_kernel(
    const float* __restrict__ x,
    const int*   __restrict__ boundaries,
    const int*   __restrict__ slot_mask,
    float*       __restrict__ out)
{
    const int k   = blockIdx.x;
    const int b   = blockIdx.y;
    const int tid = threadIdx.x;     // h index

    const int sidx  = b * KSLOT + k;
    const int start = boundaries[sidx * 2];
    const int end   = boundaries[sidx * 2 + 1];
    const int mask  = slot_mask[sidx];

    float* o = out + (size_t)sidx * HH;
    if (mask <= 0 || start >= end) { o[tid] = 0.f; return; }

    const float* xb  = x    + (size_t)b * TT * HH;
    const float* eb  = d_e  + b * TT;
    const float* Sb1 = d_S  + (size_t)b * NB1 * HH;
    const float* Eb1 = d_E  + b * NB1;
    const float* Sb2 = d_S2 + (size_t)b * NSB * HH;
    const float* Eb2 = d_E2 + b * NSB;

    float acc = 0.f, den = 0.f;

    auto tokens = [&](int t0, int t1) {
        float ea = 0.f, ec = 0.f, da = 0.f, dc = 0.f;
        int t = t0;
        for (; t + 2 <= t1; t += 2) {
            const float e0 = eb[t], e1 = eb[t + 1];
            ea += e0 * xb[(size_t)(t)     * HH + tid]; da += e0;
            ec += e1 * xb[(size_t)(t + 1) * HH + tid]; dc += e1;
        }
        if (t < t1) { const float e = eb[t]; ea += e * xb[(size_t)t * HH + tid]; da += e; }
        acc += ea + ec; den += da + dc;
    };
    auto blocks = [&](int i0, int i1) {
        float a0 = 0.f, a1 = 0.f, d0 = 0.f, d1 = 0.f;
        int i = i0;
        for (; i + 2 <= i1; i += 2) {
            a0 += Sb1[(size_t)(i)     * HH + tid]; d0 += Eb1[i];
            a1 += Sb1[(size_t)(i + 1) * HH + tid]; d1 += Eb1[i + 1];
        }
        if (i < i1) { a0 += Sb1[(size_t)i * HH + tid]; d0 += Eb1[i]; }
        acc += a0 + a1; den += d0 + d1;
    };

    const int fb = (start + 15) >> 4;
    const int lb = end >> 4;

    if (fb >= lb) {
        tokens(start, end);
    } else {
        tokens(start, fb * 16);
        tokens(lb * 16, end);

        const int fs = (fb + 15) >> 4;
        const int ls = lb >> 4;
        if (fs >= ls) {
            blocks(fb, lb);
        } else {
            blocks(fb, fs * 16);
            blocks(ls * 16, lb);
            float a0 = 0.f, a1 = 0.f, a2 = 0.f, a3 = 0.f;
            float d0 = 0.f, d1 = 0.f, d2 = 0.f, d3 = 0.f;
            int i = fs;
            for (; i + 4 <= ls; i += 4) {
                a0 += Sb2[(size_t)(i + 0) * HH + tid]; d0 += Eb2[i + 0];
                a1 += Sb2[(size_t)(i + 1) * HH + tid]; d1 += Eb2[i + 1];
                a2 += Sb2[(size_t)(i + 2) * HH + tid]; d2 += Eb2[i + 2];
                a3 += Sb2[(size_t)(i + 3) * HH + tid]; d3 += Eb2[i + 3];
            }
            for (; i < ls; i++) { a0 += Sb2[(size_t)i * HH + tid]; d0 += Eb2[i]; }
            acc += (a0 + a1) + (a2 + a3);
            den += (d0 + d1) + (d2 + d3);
        }
    }

    o[tid] = acc / den;   // den > 0: end > start and all e_t > 0
}

extern "C" void kernel_launch(void* const* d_in, const int* in_sizes, int n_in,
                              void* d_out, int out_size)
{
    const float* x          = (const float*)d_in[0];
    const int*   boundaries = (const int*)d_in[1];
    const int*   slot_mask  = (const int*)d_in[2];
    const float* W1         = (const float*)d_in[3];
    const float* b1         = (const float*)d_in[4];
    const float* W2         = (const float*)d_in[5];
    const float* b2         = (const float*)d_in[6];
    float* out = (float*)d_out;

    cudaFuncSetAttribute(pass_a_kernel,
                         cudaFuncAttributeMaxDynamicSharedMemorySize,
                         SMEM_A_BYTES);

    pass_a_kernel<<<296, 256, SMEM_A_BYTES>>>(x, W1, b1, W2, b2);
    pass_ab_kernel<<<BATCH * NSB, 256>>>();
    pass_b_kernel<<<dim3(KSLOT, BATCH), 256>>>(x, boundaries, slot_mask, out);
}